// round 7
// baseline (speedup 1.0000x reference)
#include <cuda_runtime.h>

// Problem constants (B=16, N=325, H=8, L=24, DK=DV=64)
#define L_    24
#define DK_   64
#define DV_   64
#define NT_   41600               /* tiles */
#define QK_   1536                /* floats per Q/K/V tile */
#define MS_   576                 /* floats per mask/res/scores tile */

#define SQ    68                  /* padded row stride for Q/K smem */
#define SA    28                  /* padded row stride for attn scratch */
#define TPW   4512                /* smem floats per warp: 1632+1632+1248 */

static const long long CTX_ELEMS = (long long)NT_ * QK_;   // 63,897,600

__global__ __launch_bounds__(128, 3)
void satt_kernel(const float* __restrict__ Qg, const float* __restrict__ Kg,
                 const float* __restrict__ Vg, const float* __restrict__ Mg,
                 const float* __restrict__ Rg,
                 float* __restrict__ Cg, float* __restrict__ Sg)
{
    extern __shared__ float smem[];

    const int lane = threadIdx.x & 31;
    const int wid  = threadIdx.x >> 5;
    const int tile = blockIdx.x * 4 + wid;

    float* const myQ = smem + wid * TPW;
    float* const myK = myQ + L_ * SQ;
    float* const sMk = myK + L_ * SQ;    // mask; later raw masked scores   [0,576)
    float* const sRs = sMk + 576;        // res                              [576,1152)
    float* const sAt = sRs;              // attn (stride 28) overwrites res  [576,1248)

    // ---------------- staging: Q,K -> smem; mask,res -> scratch ----------------
    {
        const float4* Q4 = reinterpret_cast<const float4*>(Qg + (size_t)tile * QK_);
        const float4* K4 = reinterpret_cast<const float4*>(Kg + (size_t)tile * QK_);
#pragma unroll
        for (int it = 0; it < 12; ++it) {
            int e = lane + it * 32;            // f4 index 0..383
            int q = e >> 4, d = (e & 15) << 2;
            *reinterpret_cast<float4*>(&myQ[q * SQ + d]) = Q4[e];
            *reinterpret_cast<float4*>(&myK[q * SQ + d]) = K4[e];
        }
        const float4* M4 = reinterpret_cast<const float4*>(Mg + (size_t)tile * MS_);
        const float4* R4 = reinterpret_cast<const float4*>(Rg + (size_t)tile * MS_);
#pragma unroll
        for (int it = 0; it < 4; ++it) {
            int e = lane + it * 32;
            reinterpret_cast<float4*>(sMk)[e] = M4[e];
            reinterpret_cast<float4*>(sRs)[e] = R4[e];
        }
        if (lane < 16) {
            reinterpret_cast<float4*>(sMk)[128 + lane] = M4[128 + lane];
            reinterpret_cast<float4*>(sRs)[128 + lane] = R4[128 + lane];
        }
    }
    __syncwarp();

    // ---------------- QK^T: TQ=6 x TK=3 over the full warp ----------------
    const int qg = lane >> 3;               // 0..3
    const int kg = lane & 7;                // 0..7
    const int q0 = qg * 6, k0 = kg * 3;
    float acc[6][3] = {};
#pragma unroll
    for (int d4 = 0; d4 < 16; ++d4) {
        const int d = d4 << 2;
        float4 qv[6], kv[3];
#pragma unroll
        for (int i = 0; i < 6; ++i) qv[i] = *reinterpret_cast<const float4*>(&myQ[(q0 + i) * SQ + d]);
#pragma unroll
        for (int j = 0; j < 3; ++j) kv[j] = *reinterpret_cast<const float4*>(&myK[(k0 + j) * SQ + d]);
#pragma unroll
        for (int i = 0; i < 6; ++i)
#pragma unroll
            for (int j = 0; j < 3; ++j) {
                acc[i][j] = fmaf(qv[i].x, kv[j].x, acc[i][j]);
                acc[i][j] = fmaf(qv[i].y, kv[j].y, acc[i][j]);
                acc[i][j] = fmaf(qv[i].z, kv[j].z, acc[i][j]);
                acc[i][j] = fmaf(qv[i].w, kv[j].w, acc[i][j]);
            }
    }

    // ---------------- epilogue: scale + res + mask (reads scratch) ----------------
#pragma unroll
    for (int i = 0; i < 6; ++i)
#pragma unroll
        for (int j = 0; j < 3; ++j) {
            const int idx = (q0 + i) * L_ + k0 + j;
            float s = fmaf(acc[i][j], 0.125f, sRs[idx]);
            if (sMk[idx] > 0.5f) s = -1e9f;
            acc[i][j] = s;
        }
    __syncwarp();                            // all mask/res reads done before overwrites

    // raw masked scores -> scratch (overwrites mask region)
#pragma unroll
    for (int i = 0; i < 6; ++i)
#pragma unroll
        for (int j = 0; j < 3; ++j)
            sMk[(q0 + i) * L_ + k0 + j] = acc[i][j];

    // ---------------- softmax over q: in-register butterfly ----------------
    float mk[3], sk[3];
#pragma unroll
    for (int j = 0; j < 3; ++j) {
        float m = acc[0][j];
#pragma unroll
        for (int i = 1; i < 6; ++i) m = fmaxf(m, acc[i][j]);
        m = fmaxf(m, __shfl_xor_sync(0xffffffffu, m, 8));
        m = fmaxf(m, __shfl_xor_sync(0xffffffffu, m, 16));
        mk[j] = m;
    }
#pragma unroll
    for (int j = 0; j < 3; ++j) {
        float s = 0.0f;
#pragma unroll
        for (int i = 0; i < 6; ++i) {
            acc[i][j] = __expf(acc[i][j] - mk[j]);
            s += acc[i][j];
        }
        s += __shfl_xor_sync(0xffffffffu, s, 8);
        s += __shfl_xor_sync(0xffffffffu, s, 16);
        sk[j] = __fdividef(1.0f, s);
    }
    __syncwarp();                            // raw score stores visible to all lanes

    // attn -> scratch (stride 28, conflict-free) ; raw scores -> global (coalesced f4)
#pragma unroll
    for (int i = 0; i < 6; ++i)
#pragma unroll
        for (int j = 0; j < 3; ++j)
            sAt[(q0 + i) * SA + k0 + j] = acc[i][j] * sk[j];
    {
        float4* S4 = reinterpret_cast<float4*>(Sg + (size_t)tile * MS_);
        const float4* sMk4 = reinterpret_cast<const float4*>(sMk);
#pragma unroll
        for (int it = 0; it < 4; ++it) {
            int e = lane + it * 32;
            S4[e] = sMk4[e];
        }
        if (lane < 16) S4[128 + lane] = sMk4[128 + lane];
    }
    __syncwarp();                            // attn visible to all lanes

    // ---------------- C = A·V : TQ=6 x TV=8, V streamed from global with prefetch ----------------
    {
        const float4* V4 = reinterpret_cast<const float4*>(Vg + (size_t)tile * QK_);
        const int vg2 = (lane & 7) * 2;      // f4 column index (16 f4 per 64-float row)
        float4 c[6][2];
#pragma unroll
        for (int i = 0; i < 6; ++i) {
            c[i][0] = make_float4(0.f, 0.f, 0.f, 0.f);
            c[i][1] = make_float4(0.f, 0.f, 0.f, 0.f);
        }
        float4 p00 = V4[vg2],      p01 = V4[vg2 + 1];
        float4 p10 = V4[16 + vg2], p11 = V4[16 + vg2 + 1];
#pragma unroll
        for (int kc = 0; kc < L_; kc += 2) {
            const float4 v00 = p00, v01 = p01, v10 = p10, v11 = p11;
            if (kc < L_ - 2) {
                p00 = V4[(kc + 2) * 16 + vg2];
                p01 = V4[(kc + 2) * 16 + vg2 + 1];
                p10 = V4[(kc + 3) * 16 + vg2];
                p11 = V4[(kc + 3) * 16 + vg2 + 1];
            }
#pragma unroll
            for (int i = 0; i < 6; ++i) {
                const float2 a = *reinterpret_cast<const float2*>(&sAt[(q0 + i) * SA + kc]);
                c[i][0].x = fmaf(a.x, v00.x, c[i][0].x);
                c[i][0].y = fmaf(a.x, v00.y, c[i][0].y);
                c[i][0].z = fmaf(a.x, v00.z, c[i][0].z);
                c[i][0].w = fmaf(a.x, v00.w, c[i][0].w);
                c[i][1].x = fmaf(a.x, v01.x, c[i][1].x);
                c[i][1].y = fmaf(a.x, v01.y, c[i][1].y);
                c[i][1].z = fmaf(a.x, v01.z, c[i][1].z);
                c[i][1].w = fmaf(a.x, v01.w, c[i][1].w);
                c[i][0].x = fmaf(a.y, v10.x, c[i][0].x);
                c[i][0].y = fmaf(a.y, v10.y, c[i][0].y);
                c[i][0].z = fmaf(a.y, v10.z, c[i][0].z);
                c[i][0].w = fmaf(a.y, v10.w, c[i][0].w);
                c[i][1].x = fmaf(a.y, v11.x, c[i][1].x);
                c[i][1].y = fmaf(a.y, v11.y, c[i][1].y);
                c[i][1].z = fmaf(a.y, v11.z, c[i][1].z);
                c[i][1].w = fmaf(a.y, v11.w, c[i][1].w);
            }
        }
        float* C = Cg + (size_t)tile * QK_;
#pragma unroll
        for (int i = 0; i < 6; ++i) {
            *reinterpret_cast<float4*>(&C[(q0 + i) * DV_ + vg2 * 4])     = c[i][0];
            *reinterpret_cast<float4*>(&C[(q0 + i) * DV_ + vg2 * 4 + 4]) = c[i][1];
        }
    }
}

extern "C" void kernel_launch(void* const* d_in, const int* in_sizes, int n_in,
                              void* d_out, int out_size)
{
    (void)in_sizes; (void)n_in; (void)out_size;
    const float* Q  = (const float*)d_in[0];
    const float* K  = (const float*)d_in[1];
    const float* V  = (const float*)d_in[2];
    const float* Mm = (const float*)d_in[3];
    const float* Ra = (const float*)d_in[4];
    float* ctx    = (float*)d_out;                 // (context, scores) concatenated
    float* scores = (float*)d_out + CTX_ELEMS;

    const int smem_bytes = 4 * TPW * 4;            // 72192 B
    cudaFuncSetAttribute(satt_kernel, cudaFuncAttributeMaxDynamicSharedMemorySize, smem_bytes);
    satt_kernel<<<NT_ / 4, 128, smem_bytes>>>(Q, K, V, Mm, Ra, ctx, scores);
}

// round 8
// speedup vs baseline: 1.1436x; 1.1436x over previous
#include <cuda_runtime.h>
#include <cstdint>

// Problem constants (B=16, N=325, H=8, L=24, DK=DV=64)
#define L_    24
#define DV_   64
#define NT_   41600
#define QK_   1536                /* floats per Q/K/V tile */
#define MS_   576                 /* floats per mask/res/scores tile */

#define SQ    68                  /* padded row stride for staged Q/K */
#define SA    28                  /* padded row stride for scores/attn */
#define TPC   8                   /* tiles per CTA */
#define STGF  4416                /* floats per stage: Q 1632 | K 1632 | M 576 | R 576 */
#define OFF_K 1632
#define OFF_M 3264
#define OFF_R 3840

static const long long CTX_ELEMS = (long long)NT_ * QK_;   // 63,897,600

__device__ __forceinline__ void cpa16(uint32_t s, const float4* g) {
    asm volatile("cp.async.cg.shared.global [%0], [%1], 16;" :: "r"(s), "l"(g));
}

__global__ __launch_bounds__(128, 5)
void satt_kernel(const float* __restrict__ Qg, const float* __restrict__ Kg,
                 const float* __restrict__ Vg, const float* __restrict__ Mg,
                 const float* __restrict__ Rg,
                 float* __restrict__ Cg, float* __restrict__ Sg)
{
    __shared__ float smem[2 * STGF + 2 * 672];      // 40704 B
    float* const sS = smem + 2 * STGF;              // raw masked scores [q][k], stride 28
    float* const sA = sS + 672;                     // normalized attn,   stride 28
    const uint32_t sb = (uint32_t)__cvta_generic_to_shared(smem);

    const int tid  = threadIdx.x;
    const int lane = tid & 31;
    const int wid  = tid >> 5;
    const int tile0 = blockIdx.x * TPC;

    auto issue = [&](int buf, int tile) {
        const uint32_t b = sb + buf * (STGF * 4);
        const float4* Q4 = reinterpret_cast<const float4*>(Qg + (size_t)tile * QK_);
        const float4* K4 = reinterpret_cast<const float4*>(Kg + (size_t)tile * QK_);
#pragma unroll
        for (int it = 0; it < 3; ++it) {
            int e = tid + it * 128;                 // f4 index 0..383
            int q = e >> 4, d = (e & 15) << 2;
            cpa16(b + (uint32_t)(q * SQ + d) * 4, Q4 + e);
            cpa16(b + (uint32_t)(OFF_K + q * SQ + d) * 4, K4 + e);
        }
        const float4* M4 = reinterpret_cast<const float4*>(Mg + (size_t)tile * MS_);
        const float4* R4 = reinterpret_cast<const float4*>(Rg + (size_t)tile * MS_);
        cpa16(b + (uint32_t)(OFF_M + tid * 4) * 4, M4 + tid);
        cpa16(b + (uint32_t)(OFF_R + tid * 4) * 4, R4 + tid);
        if (tid < 16) {
            cpa16(b + (uint32_t)(OFF_M + (128 + tid) * 4) * 4, M4 + 128 + tid);
            cpa16(b + (uint32_t)(OFF_R + (128 + tid) * 4) * 4, R4 + 128 + tid);
        }
        asm volatile("cp.async.commit_group;");
    };

    issue(0, tile0);

    for (int t = 0; t < TPC; ++t) {
        const int buf  = t & 1;
        const int tile = tile0 + t;
        if (t + 1 < TPC) {
            issue(buf ^ 1, tile0 + t + 1);
            asm volatile("cp.async.wait_group 1;");
        } else {
            asm volatile("cp.async.wait_group 0;");
        }
        __syncthreads();                            // stage[buf] visible to all

        const int role = wid ^ ((blockIdx.x + t) & 3);
        float* const bQ = smem + buf * STGF;
        float* const bK = bQ + OFF_K;
        float* const bM = bQ + OFF_M;
        float* const bR = bQ + OFF_R;

        if (role < 2) {
            // ---- QK^T, k-split: this warp owns k in [role*12, role*12+12) ----
            const int q0 = (lane >> 2) * 3;         // 8 q-groups, TQ=3
            const int k0 = role * 12 + (lane & 3) * 3;  // 4 k-groups, TK=3
            float acc[3][3] = {};
#pragma unroll
            for (int d4 = 0; d4 < 16; ++d4) {
                const int d = d4 << 2;
                float4 qv[3], kv[3];
#pragma unroll
                for (int i = 0; i < 3; ++i) qv[i] = *reinterpret_cast<const float4*>(&bQ[(q0 + i) * SQ + d]);
#pragma unroll
                for (int j = 0; j < 3; ++j) kv[j] = *reinterpret_cast<const float4*>(&bK[(k0 + j) * SQ + d]);
#pragma unroll
                for (int i = 0; i < 3; ++i)
#pragma unroll
                    for (int j = 0; j < 3; ++j) {
                        acc[i][j] = fmaf(qv[i].x, kv[j].x, acc[i][j]);
                        acc[i][j] = fmaf(qv[i].y, kv[j].y, acc[i][j]);
                        acc[i][j] = fmaf(qv[i].z, kv[j].z, acc[i][j]);
                        acc[i][j] = fmaf(qv[i].w, kv[j].w, acc[i][j]);
                    }
            }
            // ---- epilogue: scale + res + mask; raw scores -> sS ----
#pragma unroll
            for (int i = 0; i < 3; ++i)
#pragma unroll
                for (int j = 0; j < 3; ++j) {
                    const int idx = (q0 + i) * L_ + k0 + j;
                    float s = fmaf(acc[i][j], 0.125f, bR[idx]);
                    if (bM[idx] > 0.5f) s = -1e9f;
                    acc[i][j] = s;
                    sS[(q0 + i) * SA + k0 + j] = s;
                }
            // ---- softmax over q: in-register butterfly over the 8 q-groups ----
#pragma unroll
            for (int j = 0; j < 3; ++j) {
                float m = fmaxf(fmaxf(acc[0][j], acc[1][j]), acc[2][j]);
                m = fmaxf(m, __shfl_xor_sync(0xffffffffu, m, 4));
                m = fmaxf(m, __shfl_xor_sync(0xffffffffu, m, 8));
                m = fmaxf(m, __shfl_xor_sync(0xffffffffu, m, 16));
                float s = 0.0f;
#pragma unroll
                for (int i = 0; i < 3; ++i) {
                    acc[i][j] = __expf(acc[i][j] - m);
                    s += acc[i][j];
                }
                s += __shfl_xor_sync(0xffffffffu, s, 4);
                s += __shfl_xor_sync(0xffffffffu, s, 8);
                s += __shfl_xor_sync(0xffffffffu, s, 16);
                const float r = __fdividef(1.0f, s);
#pragma unroll
                for (int i = 0; i < 3; ++i)
                    sA[(q0 + i) * SA + k0 + j] = acc[i][j] * r;
            }
        } else {
            // ---- idle warps warm L1 with the V tile (48 x 128B lines) ----
            const int hw = ((role - 2) << 5) | lane;
            if (hw < 48) {
                const float* p = Vg + (size_t)tile * QK_ + hw * 32;
                asm volatile("prefetch.global.L1 [%0];" :: "l"(p));
            }
        }
        __syncthreads();                            // sS/sA ready; stage reads done

        if (role >= 2) {
            // ---- raw masked scores -> global (coalesced float4) ----
            const int hw = ((role - 2) << 5) | lane;   // 0..63
            float4* S4 = reinterpret_cast<float4*>(Sg + (size_t)tile * MS_);
#pragma unroll
            for (int it = 0; it < 2; ++it) {
                int e = hw + it * 64;
                int q = e / 6, kk = (e % 6) * 4;
                S4[e] = *reinterpret_cast<const float4*>(&sS[q * SA + kk]);
            }
            if (hw < 16) {
                int e = hw + 128;
                int q = e / 6, kk = (e % 6) * 4;
                S4[e] = *reinterpret_cast<const float4*>(&sS[q * SA + kk]);
            }
        }

        // ---- C = A·V on all 4 warps; V streamed from global (L1-warm) ----
        {
            const int q0 = (lane >> 2) * 3;
            const int v4 = (wid << 2) + (lane & 3);       // f4 column 0..15
            const float4* V4 = reinterpret_cast<const float4*>(Vg + (size_t)tile * QK_);
            float4 c0 = make_float4(0.f, 0.f, 0.f, 0.f), c1 = c0, c2 = c0;
#pragma unroll 8
            for (int k = 0; k < L_; ++k) {
                const float4 vv = V4[k * 16 + v4];
                const float a0 = sA[(q0 + 0) * SA + k];
                const float a1 = sA[(q0 + 1) * SA + k];
                const float a2 = sA[(q0 + 2) * SA + k];
                c0.x = fmaf(a0, vv.x, c0.x);
                c0.y = fmaf(a0, vv.y, c0.y);
                c0.z = fmaf(a0, vv.z, c0.z);
                c0.w = fmaf(a0, vv.w, c0.w);
                c1.x = fmaf(a1, vv.x, c1.x);
                c1.y = fmaf(a1, vv.y, c1.y);
                c1.z = fmaf(a1, vv.z, c1.z);
                c1.w = fmaf(a1, vv.w, c1.w);
                c2.x = fmaf(a2, vv.x, c2.x);
                c2.y = fmaf(a2, vv.y, c2.y);
                c2.z = fmaf(a2, vv.z, c2.z);
                c2.w = fmaf(a2, vv.w, c2.w);
            }
            float* C = Cg + (size_t)tile * QK_;
            *reinterpret_cast<float4*>(&C[(q0 + 0) * DV_ + v4 * 4]) = c0;
            *reinterpret_cast<float4*>(&C[(q0 + 1) * DV_ + v4 * 4]) = c1;
            *reinterpret_cast<float4*>(&C[(q0 + 2) * DV_ + v4 * 4]) = c2;
        }
        // next iteration's leading __syncthreads() separates sS/sA + stage reuse
    }
}

extern "C" void kernel_launch(void* const* d_in, const int* in_sizes, int n_in,
                              void* d_out, int out_size)
{
    (void)in_sizes; (void)n_in; (void)out_size;
    const float* Q  = (const float*)d_in[0];
    const float* K  = (const float*)d_in[1];
    const float* V  = (const float*)d_in[2];
    const float* Mm = (const float*)d_in[3];
    const float* Ra = (const float*)d_in[4];
    float* ctx    = (float*)d_out;                 // (context, scores) concatenated
    float* scores = (float*)d_out + CTX_ELEMS;
    satt_kernel<<<NT_ / TPC, 128>>>(Q, K, V, Mm, Ra, ctx, scores);
}